// round 17
// baseline (speedup 1.0000x reference)
#include <cuda_runtime.h>
#include <cuda_fp16.h>
#include <cstdint>
#include <cstddef>

#define NN 50000
#define NE 800000
#define DIN 128
#define DHID 512
#define DOUT 256
#define SCAN_NB ((NN + 255) / 256)   // 196

// ---------------------------------------------------------------------------
// Scratch (device globals — no runtime allocation)
// ---------------------------------------------------------------------------
__device__ __half g_xh[(size_t)NN * DIN];        // x fp16 (gather source)
__device__ __half g_xhi[(size_t)NN * DIN];       // (x+agg) fp16
__device__ __half g_h2[(size_t)NN * DOUT];       // after layer2+act (fp16)
__device__ __half g_w1hi[(size_t)DHID * DIN];    // W1^T [N][K] fp16
__device__ __half g_w2hi[(size_t)DOUT * DHID];   // W2^T [N][K] fp16
__device__ float g_sum[DOUT];
__device__ float g_sumsq[DOUT];
// CSR build
__device__ int g_deg[NN];
__device__ int g_off[NN + 1];
__device__ int g_cur[NN];
__device__ int g_srcs[NE];
// decoupled-lookback scan state
__device__ int g_ctr;
__device__ volatile int g_flag[SCAN_NB];   // 0=none, 1=aggregate, 2=inclusive
__device__ volatile int g_aggv[SCAN_NB];
__device__ volatile int g_incv[SCAN_NB];

// ---------------------------------------------------------------------------
// PTX helpers
// ---------------------------------------------------------------------------
__device__ __forceinline__ uint32_t smem_u32(const void* p) {
    uint32_t a;
    asm("{ .reg .u64 t; cvta.to.shared.u64 t, %1; cvt.u32.u64 %0, t; }"
        : "=r"(a) : "l"(p));
    return a;
}
__device__ __forceinline__ void cp_async16(uint32_t dst, const void* src, bool pred) {
    int sz = pred ? 16 : 0;
    asm volatile("cp.async.cg.shared.global [%0], [%1], 16, %2;"
                 :: "r"(dst), "l"(src), "r"(sz));
}
__device__ __forceinline__ void cp_commit() {
    asm volatile("cp.async.commit_group;" ::: "memory");
}
__device__ __forceinline__ void cp_wait0() {
    asm volatile("cp.async.wait_group 0;" ::: "memory");
}
__device__ __forceinline__ void cp_wait1() {
    asm volatile("cp.async.wait_group 1;" ::: "memory");
}
__device__ __forceinline__ void ldsm_x4(uint32_t* r, uint32_t addr) {
    asm volatile("ldmatrix.sync.aligned.m8n8.x4.shared.b16 {%0,%1,%2,%3}, [%4];"
                 : "=r"(r[0]), "=r"(r[1]), "=r"(r[2]), "=r"(r[3]) : "r"(addr));
}
__device__ __forceinline__ void hmma(float* c, const uint32_t* a, const uint32_t* b) {
    asm volatile(
        "mma.sync.aligned.m16n8k16.row.col.f32.f16.f16.f32 "
        "{%0,%1,%2,%3}, {%4,%5,%6,%7}, {%8,%9}, {%0,%1,%2,%3};"
        : "+f"(c[0]), "+f"(c[1]), "+f"(c[2]), "+f"(c[3])
        : "r"(a[0]), "r"(a[1]), "r"(a[2]), "r"(a[3]), "r"(b[0]), "r"(b[1]));
}

// ---------------------------------------------------------------------------
// 0) zero + scan-state reset + x->fp16 + both weight transposes (one launch)
// ---------------------------------------------------------------------------
__global__ void k_zero_prep(const float* __restrict__ x,
                            const float* __restrict__ W1,
                            const float* __restrict__ W2) {
    int i = blockIdx.x * blockDim.x + threadIdx.x;
    if (i < NN) g_deg[i] = 0;
    if (i < DOUT) { g_sum[i] = 0.f; g_sumsq[i] = 0.f; }
    if (i < SCAN_NB) g_flag[i] = 0;
    if (i == 0) { g_ctr = 0; g_off[NN] = NE; }
    if (i < DIN * DHID) {           // W1^T
        int n = i / DIN, k = i % DIN;
        g_w1hi[i] = __float2half_rn(W1[(size_t)k * DHID + n]);
    }
    if (i < DHID * DOUT) {          // W2^T
        int n = i / DHID, k = i % DHID;
        g_w2hi[i] = __float2half_rn(W2[(size_t)k * DOUT + n]);
    }
    const int n4 = NN * DIN / 4;
    if (i < n4) {
        float4 v = reinterpret_cast<const float4*>(x)[i];
        __half2* o = reinterpret_cast<__half2*>(g_xh) + i * 2;
        o[0] = __halves2half2(__float2half_rn(v.x), __float2half_rn(v.y));
        o[1] = __halves2half2(__float2half_rn(v.z), __float2half_rn(v.w));
    }
}

// ---------------------------------------------------------------------------
// 1) histogram of dst degrees
// ---------------------------------------------------------------------------
__global__ void k_hist(const int* __restrict__ ei) {
    int e = blockIdx.x * blockDim.x + threadIdx.x;
    if (e < NE) atomicAdd(&g_deg[ei[NE + e]], 1);
}

// ---------------------------------------------------------------------------
// 2) single-kernel exclusive scan (decoupled lookback, dynamic block ids)
// ---------------------------------------------------------------------------
__global__ void __launch_bounds__(256) k_scan_lb() {
    __shared__ int s[256];
    __shared__ int s_bid;
    __shared__ int s_exc;
    const int tid = threadIdx.x;

    if (tid == 0) s_bid = atomicAdd(&g_ctr, 1);
    __syncthreads();
    const int bid = s_bid;

    int i = bid * 256 + tid;
    int v = (i < NN) ? g_deg[i] : 0;

    // local inclusive scan (Hillis-Steele)
    s[tid] = v;
    __syncthreads();
    #pragma unroll
    for (int d = 1; d < 256; d <<= 1) {
        int u = (tid >= d) ? s[tid - d] : 0;
        __syncthreads();
        s[tid] += u;
        __syncthreads();
    }
    const int total = s[255];

    if (tid == 0) {
        if (bid == 0) {
            g_incv[0] = total;
            __threadfence();
            g_flag[0] = 2;
            s_exc = 0;
        } else {
            g_aggv[bid] = total;
            __threadfence();
            g_flag[bid] = 1;
            // lookback
            int exc = 0;
            int j = bid - 1;
            while (true) {
                int f;
                do { f = g_flag[j]; } while (f == 0);
                __threadfence();
                if (f == 2) { exc += g_incv[j]; break; }
                exc += g_aggv[j];
                j--;
            }
            g_incv[bid] = exc + total;
            __threadfence();
            g_flag[bid] = 2;
            s_exc = exc;
        }
    }
    __syncthreads();

    if (i < NN) {
        int off = s_exc + s[tid] - v;   // exclusive prefix
        g_off[i] = off;
        g_cur[i] = off;
    }
}

// ---------------------------------------------------------------------------
// 3) bucket edges by dst
// ---------------------------------------------------------------------------
__global__ void k_bucket(const int* __restrict__ ei) {
    int e = blockIdx.x * blockDim.x + threadIdx.x;
    if (e >= NE) return;
    int dst = ei[NE + e];
    int pos = atomicAdd(&g_cur[dst], 1);
    g_srcs[pos] = ei[e];
}

// ---------------------------------------------------------------------------
// 4) aggregate: one warp per node; fp16 gather, fp32 accumulate, fp16 out
// ---------------------------------------------------------------------------
__global__ void __launch_bounds__(256) k_agg() {
    int w = (blockIdx.x * blockDim.x + threadIdx.x) >> 5;
    if (w >= NN) return;
    int lane = threadIdx.x & 31;

    float acc0, acc1, acc2, acc3;
    {
        uint2 v = *reinterpret_cast<const uint2*>(g_xh + (size_t)w * DIN + lane * 4);
        float2 f0 = __half22float2(*reinterpret_cast<__half2*>(&v.x));
        float2 f1 = __half22float2(*reinterpret_cast<__half2*>(&v.y));
        acc0 = f0.x; acc1 = f0.y; acc2 = f1.x; acc3 = f1.y;
    }
    int beg = g_off[w], end = g_off[w + 1];
    for (int base = beg; base < end; base += 32) {
        int n = end - base;
        if (n > 32) n = 32;
        int s = (lane < n) ? g_srcs[base + lane] : 0;
        #pragma unroll 4
        for (int j = 0; j < n; j++) {
            int src = __shfl_sync(0xffffffffu, s, j);
            uint2 v = *reinterpret_cast<const uint2*>(g_xh + (size_t)src * DIN + lane * 4);
            float2 f0 = __half22float2(*reinterpret_cast<__half2*>(&v.x));
            float2 f1 = __half22float2(*reinterpret_cast<__half2*>(&v.y));
            acc0 += f0.x; acc1 += f0.y; acc2 += f1.x; acc3 += f1.y;
        }
    }
    __half2* o = reinterpret_cast<__half2*>(g_xhi + (size_t)w * DIN + lane * 4);
    o[0] = __halves2half2(__float2half_rn(acc0), __float2half_rn(acc1));
    o[1] = __halves2half2(__float2half_rn(acc2), __float2half_rn(acc3));
}

// ---------------------------------------------------------------------------
// 5) FUSED MLP: per CTA m-block of 64 rows.
//    Phase 1: hmid(64x512) = lrelu(x @ W1^T + b1)  -> smem (fp16)
//    Phase 2: h2(64x256)   = lrelu(hmid @ W2^T + b2) -> global fp16 + BN stats
//    2 CTAs/SM; A of phase 2 never touches global memory.
// ---------------------------------------------------------------------------
#define FM 64
#define HROWB 1040                   // 512*2 + 16 pad (16B aligned, ldsm-safe)
#define HM_SZ (FM * HROWB)           // 66560
#define SC_OFF HM_SZ                 // scratch region base
#define XB_SZ (FM * 272)             // 17408 (x tile, 272B rows)
#define W1_STG 17408                 // 64 n-rows x 272B
#define B2_STG (256 * 80)            // 20480 (W2 chunk: 256 rows x 80B)
#define SC_SZ (2 * B2_STG)           // 40960 >= max(XB, 2*W1_STG, 2*B2_STG)
#define FU_SMEM (HM_SZ + SC_SZ)      // 107520 -> 2 CTAs/SM

__global__ void __launch_bounds__(256, 2)
k_fused(const __half* __restrict__ Ah, const __half* __restrict__ W1t,
        const float* __restrict__ b1, const __half* __restrict__ W2t,
        const float* __restrict__ b2, __half* __restrict__ Ch) {
    extern __shared__ char smem[];
    const uint32_t sb = smem_u32(smem);
    const int tid = threadIdx.x;
    const int wid = tid >> 5;
    const int lane = tid & 31;
    const int m0 = blockIdx.x * FM;
    const int M = NN;
    const uint32_t lrow = (uint32_t)(lane & 15);
    const uint32_t lchk = (uint32_t)(lane >> 4);
    const int warp_m = wid & 1;      // 2 m-groups of 32 rows
    const int warp_n = wid >> 1;     // 4 n-groups

    // ---- load x tile (64 x 128 fp16) into scratch[0..XB_SZ)
    #pragma unroll
    for (int it = 0; it < 4; it++) {
        int idx = tid + it * 256;        // 0..1023
        int row = idx >> 4;              // 0..63
        int c = idx & 15;
        int gmr = m0 + row;
        cp_async16(sb + SC_OFF + row * 272 + c * 16,
                   Ah + (size_t)gmr * DIN + c * 8, gmr < M);
    }
    cp_commit();
    cp_wait0();
    __syncthreads();

    // ---- preload A fragments for the whole K=128 (a1 dead after phase 1)
    uint32_t a1[2][8][4];
    #pragma unroll
    for (int mt = 0; mt < 2; mt++)
        #pragma unroll
        for (int ks = 0; ks < 8; ks++) {
            uint32_t r = (uint32_t)(warp_m * 32 + mt * 16) + lrow;
            ldsm_x4(a1[mt][ks], sb + SC_OFF + r * 272 + lchk * 16 + ks * 32);
        }
    __syncthreads();                     // x tile region free

    // ---- phase 1: 8 chunks of 64 output cols, W1^T ring (2 stages)
    auto load_w1 = [&](int ch) {
        const uint32_t stg = sb + SC_OFF + (ch & 1) * W1_STG;
        #pragma unroll
        for (int it = 0; it < 4; it++) {
            int idx = tid + it * 256;
            int row = idx >> 4;          // 0..63 (n-row within chunk)
            int c = idx & 15;
            cp_async16(stg + row * 272 + c * 16,
                       W1t + (size_t)(ch * 64 + row) * DIN + c * 8, true);
        }
        cp_commit();
    };

    load_w1(0);
    for (int ch = 0; ch < 8; ch++) {
        if (ch + 1 < 8) { load_w1(ch + 1); cp_wait1(); }
        else cp_wait0();
        __syncthreads();

        const uint32_t stg = sb + SC_OFF + (ch & 1) * W1_STG;
        float acc1[2][2][4];
        #pragma unroll
        for (int a = 0; a < 2; a++)
            #pragma unroll
            for (int b = 0; b < 2; b++)
                #pragma unroll
                for (int c = 0; c < 4; c++) acc1[a][b][c] = 0.f;

        #pragma unroll
        for (int ks = 0; ks < 8; ks++) {
            uint32_t bh[4];
            uint32_t r = (uint32_t)(warp_n * 16) + lrow;
            ldsm_x4(bh, stg + r * 272 + lchk * 16 + ks * 32);
            uint32_t b0h[2] = {bh[0], bh[2]}, b1h[2] = {bh[1], bh[3]};
            #pragma unroll
            for (int mt = 0; mt < 2; mt++) {
                hmma(acc1[mt][0], a1[mt][ks], b0h);
                hmma(acc1[mt][1], a1[mt][ks], b1h);
            }
        }
        // epilogue -> smem hmid (bias + lrelu + fp16)
        #pragma unroll
        for (int mt = 0; mt < 2; mt++) {
            int row = warp_m * 32 + mt * 16 + (lane >> 2);
            #pragma unroll
            for (int cf = 0; cf < 2; cf++) {
                int col = ch * 64 + warp_n * 16 + cf * 8 + 2 * (lane & 3);
                float bx = b1[col], by = b1[col + 1];
                #pragma unroll
                for (int h = 0; h < 2; h++) {
                    int r = row + h * 8;
                    float v0 = acc1[mt][cf][2 * h + 0] + bx;
                    float v1 = acc1[mt][cf][2 * h + 1] + by;
                    v0 = v0 > 0.f ? v0 : 0.01f * v0;
                    v1 = v1 > 0.f ? v1 : 0.01f * v1;
                    *reinterpret_cast<__half2*>(smem + r * HROWB + col * 2) =
                        __halves2half2(__float2half_rn(v0), __float2half_rn(v1));
                }
            }
        }
        __syncthreads();
    }

    // ---- phase 2: (64x512) @ W2^T(256x512) -> 64x256, K chunks of 32
    float acc[2][8][4];
    #pragma unroll
    for (int a = 0; a < 2; a++)
        #pragma unroll
        for (int b = 0; b < 8; b++)
            #pragma unroll
            for (int c = 0; c < 4; c++) acc[a][b][c] = 0.f;

    auto load_b2 = [&](int ch) {
        const uint32_t stg = sb + SC_OFF + (ch & 1) * B2_STG;
        #pragma unroll
        for (int it = 0; it < 4; it++) {
            int idx = tid + it * 256;    // 0..1023
            int row = idx >> 2;          // 0..255
            int c = idx & 3;
            cp_async16(stg + row * 80 + c * 16,
                       W2t + (size_t)row * DHID + ch * 32 + c * 8, true);
        }
        cp_commit();
    };

    load_b2(0);
    for (int ch = 0; ch < 16; ch++) {
        if (ch + 1 < 16) { load_b2(ch + 1); cp_wait1(); }
        else cp_wait0();
        __syncthreads();

        const uint32_t stg = sb + SC_OFF + (ch & 1) * B2_STG;
        #pragma unroll
        for (int ks = 0; ks < 2; ks++) {
            uint32_t a2[2][4];
            #pragma unroll
            for (int mt = 0; mt < 2; mt++) {
                uint32_t r = (uint32_t)(warp_m * 32 + mt * 16) + lrow;
                ldsm_x4(a2[mt], sb + r * HROWB + ch * 64 + ks * 32 + lchk * 16);
            }
            #pragma unroll
            for (int np = 0; np < 4; np++) {
                uint32_t bh[4];
                uint32_t r = (uint32_t)(warp_n * 64 + np * 16) + lrow;
                ldsm_x4(bh, stg + r * 80 + lchk * 16 + ks * 32);
                uint32_t b0h[2] = {bh[0], bh[2]}, b1h[2] = {bh[1], bh[3]};
                #pragma unroll
                for (int mt = 0; mt < 2; mt++) {
                    hmma(acc[mt][2 * np],     a2[mt], b0h);
                    hmma(acc[mt][2 * np + 1], a2[mt], b1h);
                }
            }
        }
        __syncthreads();
    }

    // ---- epilogue: bias + lrelu + fp16 store + fused BN stats
    float scol[8][2];
    float qcol[8][2];
    #pragma unroll
    for (int nt = 0; nt < 8; nt++) {
        scol[nt][0] = scol[nt][1] = 0.f;
        qcol[nt][0] = qcol[nt][1] = 0.f;
    }

    #pragma unroll
    for (int mt = 0; mt < 2; mt++) {
        int row = m0 + warp_m * 32 + mt * 16 + (lane >> 2);
        #pragma unroll
        for (int nt = 0; nt < 8; nt++) {
            int col = warp_n * 64 + nt * 8 + 2 * (lane & 3);
            float bx = b2[col], by = b2[col + 1];
            #pragma unroll
            for (int h = 0; h < 2; h++) {
                int r = row + h * 8;
                if (r >= M) continue;
                float v0 = acc[mt][nt][2 * h + 0] + bx;
                float v1 = acc[mt][nt][2 * h + 1] + by;
                v0 = v0 > 0.f ? v0 : 0.01f * v0;
                v1 = v1 > 0.f ? v1 : 0.01f * v1;
                *reinterpret_cast<__half2*>(Ch + (size_t)r * DOUT + col) =
                    __halves2half2(__float2half_rn(v0), __float2half_rn(v1));
                scol[nt][0] += v0; qcol[nt][0] += v0 * v0;
                scol[nt][1] += v1; qcol[nt][1] += v1 * v1;
            }
        }
    }

    {
        float* sarr = reinterpret_cast<float*>(smem + SC_OFF);
        float* qarr = sarr + DOUT;
        __syncthreads();
        if (tid < DOUT) { sarr[tid] = 0.f; qarr[tid] = 0.f; }
        __syncthreads();
        #pragma unroll
        for (int nt = 0; nt < 8; nt++) {
            float s0 = scol[nt][0], s1 = scol[nt][1];
            float q0 = qcol[nt][0], q1 = qcol[nt][1];
            #pragma unroll
            for (int o = 4; o < 32; o <<= 1) {
                s0 += __shfl_xor_sync(0xffffffffu, s0, o);
                s1 += __shfl_xor_sync(0xffffffffu, s1, o);
                q0 += __shfl_xor_sync(0xffffffffu, q0, o);
                q1 += __shfl_xor_sync(0xffffffffu, q1, o);
            }
            if (lane < 4) {
                int c = warp_n * 64 + nt * 8 + 2 * lane;
                atomicAdd(&sarr[c], s0);
                atomicAdd(&sarr[c + 1], s1);
                atomicAdd(&qarr[c], q0);
                atomicAdd(&qarr[c + 1], q1);
            }
        }
        __syncthreads();
        if (tid < DOUT) {
            atomicAdd(&g_sum[tid], sarr[tid]);
            atomicAdd(&g_sumsq[tid], qarr[tid]);
        }
    }
}

// ---------------------------------------------------------------------------
// 6) normalize with inline BN finalize (fp16 h2 in, fp32 out)
// ---------------------------------------------------------------------------
__global__ void __launch_bounds__(256) k_normalize(float* __restrict__ out,
                                                   const float* __restrict__ gamma,
                                                   const float* __restrict__ beta) {
    __shared__ float4 s_sc[DOUT / 4];
    __shared__ float4 s_sh[DOUT / 4];
    const int tid = threadIdx.x;
    if (tid < DOUT / 4) {
        const float invn = 1.0f / (float)NN;
        float4 sc, sh;
        #pragma unroll
        for (int k = 0; k < 4; k++) {
            int c = tid * 4 + k;
            float mean = g_sum[c] * invn;
            float var = g_sumsq[c] * invn - mean * mean;
            float rstd = rsqrtf(var + 1e-5f);
            float s = gamma[c] * rstd;
            (&sc.x)[k] = s;
            (&sh.x)[k] = beta[c] - mean * s;
        }
        s_sc[tid] = sc;
        s_sh[tid] = sh;
    }
    __syncthreads();

    int i = blockIdx.x * blockDim.x + tid;
    const int n4 = NN * DOUT / 4;
    if (i >= n4) return;
    int c4 = i & (DOUT / 4 - 1);
    uint2 hv = reinterpret_cast<const uint2*>(g_h2)[i];
    float2 f0 = __half22float2(*reinterpret_cast<__half2*>(&hv.x));
    float2 f1 = __half22float2(*reinterpret_cast<__half2*>(&hv.y));
    float4 sc = s_sc[c4];
    float4 sh = s_sh[c4];
    float4 v;
    v.x = f0.x * sc.x + sh.x;
    v.y = f0.y * sc.y + sh.y;
    v.z = f1.x * sc.z + sh.z;
    v.w = f1.y * sc.w + sh.w;
    reinterpret_cast<float4*>(out)[i] = v;
}

// ---------------------------------------------------------------------------
extern "C" void kernel_launch(void* const* d_in, const int* in_sizes, int n_in,
                              void* d_out, int out_size) {
    const float* x     = (const float*)d_in[0];
    const int*   ei    = (const int*)d_in[1];
    const float* W1    = (const float*)d_in[2];
    const float* b1    = (const float*)d_in[3];
    const float* W2    = (const float*)d_in[4];
    const float* b2    = (const float*)d_in[5];
    const float* gamma = (const float*)d_in[6];
    const float* beta  = (const float*)d_in[7];
    float* out = (float*)d_out;

    __half *xhi, *w1hi, *w2hi, *h2;
    cudaGetSymbolAddress((void**)&xhi, g_xhi);
    cudaGetSymbolAddress((void**)&w1hi, g_w1hi);
    cudaGetSymbolAddress((void**)&w2hi, g_w2hi);
    cudaGetSymbolAddress((void**)&h2, g_h2);

    cudaFuncSetAttribute(k_fused,
                         cudaFuncAttributeMaxDynamicSharedMemorySize, FU_SMEM);

    // CSR build + x->fp16 + weight prep + aggregate
    k_zero_prep<<<(NN * DIN / 4 + 255) / 256, 256>>>(x, W1, W2);
    k_hist<<<(NE + 255) / 256, 256>>>(ei);
    k_scan_lb<<<SCAN_NB, 256>>>();
    k_bucket<<<(NE + 255) / 256, 256>>>(ei);
    k_agg<<<(NN * 32 + 255) / 256, 256>>>();

    // fused MLP (GEMM1 + GEMM2 + BN stats)
    k_fused<<<(NN + FM - 1) / FM, 256, FU_SMEM>>>(xhi, w1hi, b1, w2hi, b2, h2);

    // normalize (inline BN finalize)
    k_normalize<<<(NN * DOUT / 4 + 255) / 256, 256>>>(out, gamma, beta);
}